// round 2
// baseline (speedup 1.0000x reference)
#include <cuda_runtime.h>

// Problem-fixed capacities (reference: N=100000, E=1600000, HIDDEN=128)
#define N_MAX 100000
#define E_MAX 1600000
#define HID   128
#define LEAKY 0.01f

// Scratch (device globals; no allocation allowed anywhere)
__device__ float g_si[N_MAX];      // s_i = x @ w_i
__device__ float g_sj[N_MAX];      // s_j = x @ w_j
__device__ float g_ssum[N_MAX];    // segment sum of exp(e)
__device__ int   g_cnt[N_MAX];     // edges per source node
__device__ int   g_off[N_MAX];     // exclusive prefix of g_cnt
__device__ int   g_cur[N_MAX];     // scatter cursor (copy of g_off)
__device__ float g_e[E_MAX];       // exp(leakyrelu(score)) per edge
__device__ int   g_pt[E_MAX];      // t[] permuted into h-segment order
__device__ float g_pe[E_MAX];      // exp scores permuted into h-segment order

// ---------------------------------------------------------------------------
// K0: zero per-node accumulators
// ---------------------------------------------------------------------------
__global__ void k_init(int n) {
    int tid = blockIdx.x * blockDim.x + threadIdx.x;
    int stride = gridDim.x * blockDim.x;
    for (int i = tid; i < n; i += stride) {
        g_ssum[i] = 0.0f;
        g_cnt[i]  = 0;
    }
}

// ---------------------------------------------------------------------------
// K1: per-node scores. One warp per node; lane l owns float4 chunk l.
// ---------------------------------------------------------------------------
__global__ void k_node_scores(const float* __restrict__ x,
                              const float* __restrict__ wi,
                              const float* __restrict__ wj, int n) {
    int warp = (blockIdx.x * blockDim.x + threadIdx.x) >> 5;
    int lane = threadIdx.x & 31;
    if (warp >= n) return;

    float4 xv  = __ldg(reinterpret_cast<const float4*>(x)  + warp * 32 + lane);
    float4 wiv = __ldg(reinterpret_cast<const float4*>(wi) + lane);
    float4 wjv = __ldg(reinterpret_cast<const float4*>(wj) + lane);

    float si = xv.x * wiv.x + xv.y * wiv.y + xv.z * wiv.z + xv.w * wiv.w;
    float sj = xv.x * wjv.x + xv.y * wjv.y + xv.z * wjv.z + xv.w * wjv.w;

    #pragma unroll
    for (int o = 16; o > 0; o >>= 1) {
        si += __shfl_xor_sync(0xFFFFFFFFu, si, o);
        sj += __shfl_xor_sync(0xFFFFFFFFu, sj, o);
    }
    if (lane == 0) {
        g_si[warp] = si;
        g_sj[warp] = sj;
    }
}

// ---------------------------------------------------------------------------
// K2: fused edge pass: e = leakyrelu(s_i[h]+s_j[t]); ex = exp(e);
//     seg_sum[h] += ex; count[h]++. (max-shift dropped: |e| <= ~8, fp32-safe;
//     alpha is shift-invariant in exact arithmetic)
// ---------------------------------------------------------------------------
__global__ void k_edge_pass(const int* __restrict__ h, const int* __restrict__ t,
                            int e) {
    int i = blockIdx.x * blockDim.x + threadIdx.x;
    if (i >= e) return;
    int hh = __ldg(h + i);
    int tt = __ldg(t + i);
    float v = g_si[hh] + g_sj[tt];
    v = (v > 0.0f) ? v : LEAKY * v;
    float ex = __expf(v);
    g_e[i] = ex;
    atomicAdd(&g_ssum[hh], ex);
    atomicAdd(&g_cnt[hh], 1);
}

// ---------------------------------------------------------------------------
// K3: exclusive scan of g_cnt -> g_off, g_cur. Single block of 1024 threads,
//     warp-shfl hierarchical scan, ~4 barriers per 1024-element tile.
// ---------------------------------------------------------------------------
__device__ __forceinline__ int warp_iscan(int v, int lane) {
    #pragma unroll
    for (int o = 1; o < 32; o <<= 1) {
        int u = __shfl_up_sync(0xFFFFFFFFu, v, o);
        if (lane >= o) v += u;
    }
    return v;
}

__global__ void k_scan(int n) {
    __shared__ int sh[33];     // [0..31] per-warp exclusive offsets, [32] tile total
    __shared__ int carry;
    int tid  = threadIdx.x;
    int lane = tid & 31;
    int wid  = tid >> 5;
    if (tid == 0) carry = 0;
    __syncthreads();

    for (int base = 0; base < n; base += 1024) {
        int i = base + tid;
        int v = (i < n) ? g_cnt[i] : 0;
        int incl = warp_iscan(v, lane);
        if (lane == 31) sh[wid] = incl;
        __syncthreads();
        if (wid == 0) {
            int s  = sh[lane];
            int si = warp_iscan(s, lane);
            sh[lane] = si - s;               // exclusive warp offset
            if (lane == 31) sh[32] = si;     // tile total
        }
        __syncthreads();
        int excl = carry + sh[wid] + incl - v;
        if (i < n) {
            g_off[i] = excl;
            g_cur[i] = excl;
        }
        __syncthreads();
        if (tid == 0) carry += sh[32];
        __syncthreads();
    }
}

// ---------------------------------------------------------------------------
// K4: scatter edges into h-segment-contiguous order: (t, ex) pairs
// ---------------------------------------------------------------------------
__global__ void k_scatter(const int* __restrict__ h, const int* __restrict__ t,
                          int e) {
    int i = blockIdx.x * blockDim.x + threadIdx.x;
    if (i >= e) return;
    int hh  = __ldg(h + i);
    int pos = atomicAdd(&g_cur[hh], 1);
    g_pt[pos] = __ldg(t + i);
    g_pe[pos] = g_e[i];
}

// ---------------------------------------------------------------------------
// K5: SpMM + ReLU. One warp per destination node; register accumulation,
//     single store per row, 2-edge unroll for MLP.
// ---------------------------------------------------------------------------
__global__ void k_spmm(const float* __restrict__ x, float* __restrict__ out,
                       int n) {
    int warp = (blockIdx.x * blockDim.x + threadIdx.x) >> 5;
    int lane = threadIdx.x & 31;
    if (warp >= n) return;

    int base = g_off[warp];
    int cnt  = g_cnt[warp];
    float inv = (cnt > 0) ? (1.0f / g_ssum[warp]) : 0.0f;

    const float4* x4 = reinterpret_cast<const float4*>(x);
    float4 acc = make_float4(0.f, 0.f, 0.f, 0.f);

    int j = 0;
    for (; j + 1 < cnt; j += 2) {
        int   t0 = g_pt[base + j];
        int   t1 = g_pt[base + j + 1];
        float a0 = g_pe[base + j] * inv;
        float a1 = g_pe[base + j + 1] * inv;
        float4 v0 = __ldg(x4 + t0 * 32 + lane);
        float4 v1 = __ldg(x4 + t1 * 32 + lane);
        acc.x += a0 * v0.x; acc.y += a0 * v0.y;
        acc.z += a0 * v0.z; acc.w += a0 * v0.w;
        acc.x += a1 * v1.x; acc.y += a1 * v1.y;
        acc.z += a1 * v1.z; acc.w += a1 * v1.w;
    }
    if (j < cnt) {
        int   t0 = g_pt[base + j];
        float a0 = g_pe[base + j] * inv;
        float4 v0 = __ldg(x4 + t0 * 32 + lane);
        acc.x += a0 * v0.x; acc.y += a0 * v0.y;
        acc.z += a0 * v0.z; acc.w += a0 * v0.w;
    }

    acc.x = fmaxf(acc.x, 0.f);
    acc.y = fmaxf(acc.y, 0.f);
    acc.z = fmaxf(acc.z, 0.f);
    acc.w = fmaxf(acc.w, 0.f);
    reinterpret_cast<float4*>(out)[warp * 32 + lane] = acc;
}

extern "C" void kernel_launch(void* const* d_in, const int* in_sizes, int n_in,
                              void* d_out, int out_size) {
    const float* x  = (const float*)d_in[0];
    const float* wi = (const float*)d_in[1];
    const float* wj = (const float*)d_in[2];
    const int*   h  = (const int*)d_in[3];
    const int*   t  = (const int*)d_in[4];
    float* out = (float*)d_out;

    int n = in_sizes[0] / HID;   // nodes
    int e = in_sizes[3];         // edges

    k_init<<<(n + 255) / 256, 256>>>(n);

    {   // node scores: one warp per node
        long long threads = (long long)n * 32;
        k_node_scores<<<(int)((threads + 255) / 256), 256>>>(x, wi, wj, n);
    }

    k_edge_pass<<<(e + 255) / 256, 256>>>(h, t, e);

    k_scan<<<1, 1024>>>(n);

    k_scatter<<<(e + 255) / 256, 256>>>(h, t, e);

    {   // spmm: one warp per node
        long long threads = (long long)n * 32;
        k_spmm<<<(int)((threads + 255) / 256), 256>>>(x, out, n);
    }
}

// round 16
// speedup vs baseline: 1.7129x; 1.7129x over previous
#include <cuda_runtime.h>

// Problem-fixed capacities (reference: N=100000, E=1600000, HIDDEN=128)
#define N_MAX 100000
#define E_MAX 1600000
#define HID   128
#define LEAKY 0.01f

// Scratch (device globals; no allocation allowed anywhere)
__device__ float g_si[N_MAX];      // s_i = x @ w_i
__device__ float g_sj[N_MAX];      // s_j = x @ w_j
__device__ int   g_cnt[N_MAX];     // edges per source node
__device__ int   g_off[N_MAX];     // segment base in permuted arrays
__device__ int   g_cur[N_MAX];     // scatter cursor (copy of g_off)
__device__ int   g_total;          // global bump cursor for segment bases
__device__ int2  g_pte[E_MAX];     // packed (t, float_bits(exp)) in segment order

// ---------------------------------------------------------------------------
// K1: per-node scores + count init. One warp per node; lane l owns float4
//     chunk l of the row.
// ---------------------------------------------------------------------------
__global__ void k_node_scores(const float* __restrict__ x,
                              const float* __restrict__ wi,
                              const float* __restrict__ wj, int n) {
    int warp = (blockIdx.x * blockDim.x + threadIdx.x) >> 5;
    int lane = threadIdx.x & 31;
    if (warp >= n) return;

    float4 xv  = __ldg(reinterpret_cast<const float4*>(x)  + warp * 32 + lane);
    float4 wiv = __ldg(reinterpret_cast<const float4*>(wi) + lane);
    float4 wjv = __ldg(reinterpret_cast<const float4*>(wj) + lane);

    float si = xv.x * wiv.x + xv.y * wiv.y + xv.z * wiv.z + xv.w * wiv.w;
    float sj = xv.x * wjv.x + xv.y * wjv.y + xv.z * wjv.z + xv.w * wjv.w;

    #pragma unroll
    for (int o = 16; o > 0; o >>= 1) {
        si += __shfl_xor_sync(0xFFFFFFFFu, si, o);
        sj += __shfl_xor_sync(0xFFFFFFFFu, sj, o);
    }
    if (lane == 0) {
        g_si[warp]  = si;
        g_sj[warp]  = sj;
        g_cnt[warp] = 0;
    }
}

// ---------------------------------------------------------------------------
// K2: count edges per source node (reads h only). Also resets bump cursor.
// ---------------------------------------------------------------------------
__global__ void k_count(const int* __restrict__ h, int e) {
    int i = blockIdx.x * blockDim.x + threadIdx.x;
    if (i == 0) g_total = 0;
    if (i >= e) return;
    atomicAdd(&g_cnt[__ldg(h + i)], 1);
}

// ---------------------------------------------------------------------------
// K3: segment base assignment WITHOUT a global prefix sum. Each 256-thread
//     block scans its 256 counts locally (shfl), then bumps g_total once.
//     Segments end up contiguous; their order in scratch is irrelevant.
// ---------------------------------------------------------------------------
__device__ __forceinline__ int warp_iscan(int v, int lane) {
    #pragma unroll
    for (int o = 1; o < 32; o <<= 1) {
        int u = __shfl_up_sync(0xFFFFFFFFu, v, o);
        if (lane >= o) v += u;
    }
    return v;
}

__global__ void k_offsets(int n) {
    __shared__ int warp_base[8];   // per-warp exclusive offsets within block
    __shared__ int block_base;
    int tid  = threadIdx.x;
    int lane = tid & 31;
    int wid  = tid >> 5;
    int i = blockIdx.x * blockDim.x + tid;

    int v    = (i < n) ? g_cnt[i] : 0;
    int incl = warp_iscan(v, lane);
    if (lane == 31) warp_base[wid] = incl;   // warp totals
    __syncthreads();

    if (tid < 8) {
        int s  = warp_base[tid];
        int si = s;
        #pragma unroll
        for (int o = 1; o < 8; o <<= 1) {
            int u = __shfl_up_sync(0xFFu, si, o, 8);
            if (tid >= o) si += u;
        }
        warp_base[tid] = si - s;             // exclusive warp offset
        if (tid == 7) block_base = atomicAdd(&g_total, si);  // one atomic/block
    }
    __syncthreads();

    if (i < n) {
        int off = block_base + warp_base[wid] + incl - v;
        g_off[i] = off;
        g_cur[i] = off;
    }
}

// ---------------------------------------------------------------------------
// K4: fused score + exp + scatter.
//     e = leakyrelu(s_i[h]+s_j[t]); ex = exp(e); write packed (t, ex) into
//     segment-contiguous position. No ssum atomic: normalization happens in
//     the SpMM (out = Σ ex·x / Σ ex, exactly equal to Σ (ex/Σex)·x).
//     Max-shift dropped: scores are O(1)-scaled (|e| <~ 8) so exp() is
//     fp32-safe; alpha is exactly shift-invariant.
// ---------------------------------------------------------------------------
__global__ void k_scatter(const int* __restrict__ h, const int* __restrict__ t,
                          int e) {
    int i = blockIdx.x * blockDim.x + threadIdx.x;
    if (i >= e) return;
    int hh = __ldg(h + i);
    int tt = __ldg(t + i);
    float v = g_si[hh] + g_sj[tt];
    v = (v > 0.0f) ? v : LEAKY * v;
    float ex = __expf(v);
    int pos = atomicAdd(&g_cur[hh], 1);
    g_pte[pos] = make_int2(tt, __float_as_int(ex));
}

// ---------------------------------------------------------------------------
// K5: SpMM + normalize + ReLU. One warp per destination node; register
//     accumulation of both Σ ex·x and Σ ex, single store per row,
//     4-edge unroll for MLP.
// ---------------------------------------------------------------------------
__global__ void k_spmm(const float* __restrict__ x, float* __restrict__ out,
                       int n) {
    int warp = (blockIdx.x * blockDim.x + threadIdx.x) >> 5;
    int lane = threadIdx.x & 31;
    if (warp >= n) return;

    int base = g_off[warp];
    int cnt  = g_cnt[warp];

    const float4* x4 = reinterpret_cast<const float4*>(x);
    float4 acc = make_float4(0.f, 0.f, 0.f, 0.f);
    float sexp = 0.f;

    int j = 0;
    for (; j + 3 < cnt; j += 4) {
        int2 p0 = g_pte[base + j];
        int2 p1 = g_pte[base + j + 1];
        int2 p2 = g_pte[base + j + 2];
        int2 p3 = g_pte[base + j + 3];
        float a0 = __int_as_float(p0.y);
        float a1 = __int_as_float(p1.y);
        float a2 = __int_as_float(p2.y);
        float a3 = __int_as_float(p3.y);
        float4 v0 = __ldg(x4 + p0.x * 32 + lane);
        float4 v1 = __ldg(x4 + p1.x * 32 + lane);
        float4 v2 = __ldg(x4 + p2.x * 32 + lane);
        float4 v3 = __ldg(x4 + p3.x * 32 + lane);
        sexp += a0 + a1 + a2 + a3;
        acc.x += a0 * v0.x; acc.y += a0 * v0.y; acc.z += a0 * v0.z; acc.w += a0 * v0.w;
        acc.x += a1 * v1.x; acc.y += a1 * v1.y; acc.z += a1 * v1.z; acc.w += a1 * v1.w;
        acc.x += a2 * v2.x; acc.y += a2 * v2.y; acc.z += a2 * v2.z; acc.w += a2 * v2.w;
        acc.x += a3 * v3.x; acc.y += a3 * v3.y; acc.z += a3 * v3.z; acc.w += a3 * v3.w;
    }
    for (; j < cnt; j++) {
        int2 p0 = g_pte[base + j];
        float a0 = __int_as_float(p0.y);
        float4 v0 = __ldg(x4 + p0.x * 32 + lane);
        sexp += a0;
        acc.x += a0 * v0.x; acc.y += a0 * v0.y; acc.z += a0 * v0.z; acc.w += a0 * v0.w;
    }

    float inv = (cnt > 0) ? (1.0f / sexp) : 0.0f;
    acc.x = fmaxf(acc.x * inv, 0.f);
    acc.y = fmaxf(acc.y * inv, 0.f);
    acc.z = fmaxf(acc.z * inv, 0.f);
    acc.w = fmaxf(acc.w * inv, 0.f);
    reinterpret_cast<float4*>(out)[warp * 32 + lane] = acc;
}

extern "C" void kernel_launch(void* const* d_in, const int* in_sizes, int n_in,
                              void* d_out, int out_size) {
    const float* x  = (const float*)d_in[0];
    const float* wi = (const float*)d_in[1];
    const float* wj = (const float*)d_in[2];
    const int*   h  = (const int*)d_in[3];
    const int*   t  = (const int*)d_in[4];
    float* out = (float*)d_out;

    int n = in_sizes[0] / HID;   // nodes
    int e = in_sizes[3];         // edges

    {   // node scores + init: one warp per node
        long long threads = (long long)n * 32;
        k_node_scores<<<(int)((threads + 255) / 256), 256>>>(x, wi, wj, n);
    }

    k_count<<<(e + 255) / 256, 256>>>(h, e);

    k_offsets<<<(n + 255) / 256, 256>>>(n);

    k_scatter<<<(e + 255) / 256, 256>>>(h, t, e);

    {   // spmm: one warp per node
        long long threads = (long long)n * 32;
        k_spmm<<<(int)((threads + 255) / 256), 256>>>(x, out, n);
    }
}